// round 14
// baseline (speedup 1.0000x reference)
#include <cuda_runtime.h>
#include <math.h>
#include <stdint.h>

// ---------------------------------------------------------------------------
// Problem constants: x (64,128,32,32) -> h (64,256,32,32) -> mixture of ops
// ---------------------------------------------------------------------------
#define BATCH 64
#define CIN_X 128
#define CCH   256
#define HW    32
#define PLANE 1024                 // 32*32
#define NPLANES (BATCH*CCH)        // 16384
#define NTOT (16777216u)           // 64*256*32*32
#define NHW  65536                 // per-channel element count (B*H*W)

typedef unsigned long long u64;

// Packed fp32x2 FMA (Blackwell sm_100+): d = a*b + d on two packed fp32 lanes.
__device__ __forceinline__ void ffma2(u64& d, u64 a, u64 b) {
    asm("fma.rn.f32x2 %0, %1, %2, %0;" : "+l"(d) : "l"(a), "l"(b));
}
__device__ __forceinline__ u64 bcast2(float v) {
    u64 r; uint32_t iv = __float_as_uint(v);
    asm("mov.b64 %0, {%1, %1};" : "=l"(r) : "r"(iv));
    return r;
}
__device__ __forceinline__ void unpack2(u64 p, float& lo, float& hi) {
    asm("mov.b64 {%0, %1}, %2;" : "=f"(lo), "=f"(hi) : "l"(p));
}

// Scratch buffers (device globals: allocation-free)
__device__ float g_h[NTOT];   // activation after input transition (BN+ReLU)
__device__ float g_y[NTOT];   // per-op scratch
__device__ float g_t[NTOT];   // depthwise intermediate for sep_conv
__device__ float g_sel[8];    // thresholded/renormalized mixture weights
__device__ float g_A[CCH];    // per-channel fused BN scale
__device__ float g_B[CCH];    // per-channel fused BN shift

// ---------------------------------------------------------------------------
// sel computation: softmax -> top-3 -> threshold 0.01 -> renormalize
// ---------------------------------------------------------------------------
__global__ void sel_kernel(const float* __restrict__ aw) {
    if (threadIdx.x != 0) return;
    float w[8];
    float mx = -1e30f;
    for (int i = 0; i < 8; i++) { w[i] = aw[i]; mx = fmaxf(mx, w[i]); }
    float s = 0.f;
    for (int i = 0; i < 8; i++) { w[i] = expf(w[i] - mx); s += w[i]; }
    for (int i = 0; i < 8; i++) w[i] /= s;
    float sel[8]; float tmp[8];
    for (int i = 0; i < 8; i++) { sel[i] = 0.f; tmp[i] = w[i]; }
    for (int t = 0; t < 3; t++) {
        int bi = 0; float bv = tmp[0];
        for (int i = 1; i < 8; i++) if (tmp[i] > bv) { bv = tmp[i]; bi = i; }
        sel[bi] = bv; tmp[bi] = -1e30f;
    }
    float ssum = 0.f;
    for (int i = 0; i < 8; i++) { if (sel[i] < 0.01f) sel[i] = 0.f; ssum += sel[i]; }
    ssum = fmaxf(ssum, 1e-12f);
    for (int i = 0; i < 8; i++) g_sel[i] = sel[i] / ssum;
}

// ---------------------------------------------------------------------------
// Implicit-GEMM conv with packed f32x2 FMAs.
// Tile: 64 Cout x (4 rows x 32 cols). 256 threads; each thread 4 cout-pairs x 4sp.
// ---------------------------------------------------------------------------
template<int KH, int KW, int DIL, int CI>
__global__ void conv_kernel(const float* __restrict__ in,
                            const float* __restrict__ wgt,
                            float* __restrict__ outp,
                            int Cin, int Cout, int selIdx) {
    if (selIdx >= 0 && g_sel[selIdx] == 0.0f) return;
    constexpr int PAD = DIL * (KH - 1) / 2;
    constexpr int TH  = 4;
    constexpr int IR  = TH + 2 * PAD;
    constexpr int IC  = HW + 2 * PAD;
    constexpr int KK  = KH * KW;

    __shared__ __align__(16) float ws[CI][KK][68];   // 68-pad vs conflicts; rows 16B-mult
    __shared__ __align__(16) float is[CI][IR][IC];

    const int rt  = blockIdx.x;            // row tile (0..7)
    const int n   = blockIdx.y;            // image
    const int co0 = blockIdx.z * 64;       // cout tile
    const int y0  = rt * TH;

    const int t   = threadIdx.x;
    const int cg  = t & 7;                 // cout group (x8)
    const int sg  = t >> 3;                // spatial group (x4)
    const int y_l = sg >> 3;               // 0..3
    const int x0  = (sg * 4) & 31;

    u64 acc2[4][4];                        // [cout-pair][spatial], packed {lo,hi}
#pragma unroll
    for (int a = 0; a < 4; a++)
#pragma unroll
        for (int j = 0; j < 4; j++) acc2[a][j] = 0ULL;

    for (int ci0 = 0; ci0 < Cin; ci0 += CI) {
        __syncthreads();
        // weights: contiguous CI*KK floats per cout row
        for (int idx = t; idx < 64 * CI * KK; idx += 256) {
            int r    = idx % (CI * KK);
            int co_l = idx / (CI * KK);
            int ci   = r / KK;
            int kk   = r % KK;
            ws[ci][kk][co_l] =
                wgt[((size_t)(co0 + co_l) * Cin + ci0) * KK + r];
        }
        // input tile with zero padding
        for (int idx = t; idx < CI * IR * IC; idx += 256) {
            int c  = idx % IC;
            int r  = (idx / IC) % IR;
            int ci = idx / (IC * IR);
            int yy = y0 - PAD + r;
            int xx = c - PAD;
            float v = 0.f;
            if (yy >= 0 && yy < HW && xx >= 0 && xx < HW)
                v = in[(((size_t)n * Cin + ci0 + ci) * HW + yy) * HW + xx];
            is[ci][r][c] = v;
        }
        __syncthreads();

#pragma unroll 1
        for (int ci = 0; ci < CI; ci++) {
#pragma unroll
            for (int ky = 0; ky < KH; ky++) {
#pragma unroll
                for (int kx = 0; kx < KW; kx++) {
                    // 8 consecutive couts = 4 aligned 64-bit pairs in smem
                    const u64* wp = reinterpret_cast<const u64*>(&ws[ci][ky*KW+kx][cg*8]);
                    const u64 w0 = wp[0], w1 = wp[1], w2 = wp[2], w3 = wp[3];
                    const float* ip = &is[ci][y_l + ky*DIL][x0 + kx*DIL];
                    const u64 b0 = bcast2(ip[0]);
                    const u64 b1 = bcast2(ip[1]);
                    const u64 b2 = bcast2(ip[2]);
                    const u64 b3 = bcast2(ip[3]);
                    ffma2(acc2[0][0], w0, b0); ffma2(acc2[0][1], w0, b1);
                    ffma2(acc2[0][2], w0, b2); ffma2(acc2[0][3], w0, b3);
                    ffma2(acc2[1][0], w1, b0); ffma2(acc2[1][1], w1, b1);
                    ffma2(acc2[1][2], w1, b2); ffma2(acc2[1][3], w1, b3);
                    ffma2(acc2[2][0], w2, b0); ffma2(acc2[2][1], w2, b1);
                    ffma2(acc2[2][2], w2, b2); ffma2(acc2[2][3], w2, b3);
                    ffma2(acc2[3][0], w3, b0); ffma2(acc2[3][1], w3, b1);
                    ffma2(acc2[3][2], w3, b2); ffma2(acc2[3][3], w3, b3);
                }
            }
        }
    }

    // unpack into per-cout rows and store float4 per row
    float accf[8][4];
#pragma unroll
    for (int a = 0; a < 4; a++)
#pragma unroll
        for (int j = 0; j < 4; j++)
            unpack2(acc2[a][j], accf[2*a][j], accf[2*a+1][j]);

#pragma unroll
    for (int a = 0; a < 8; a++) {
        const int co = co0 + cg*8 + a;
        float4 v = make_float4(accf[a][0], accf[a][1], accf[a][2], accf[a][3]);
        *reinterpret_cast<float4*>(
            &outp[(((size_t)n * Cout + co) * HW + y0 + y_l) * HW + x0]) = v;
    }
}

// ---------------------------------------------------------------------------
// Depthwise 3x3 conv (pad 1), one plane per block
// ---------------------------------------------------------------------------
__global__ void dwconv_kernel(const float* __restrict__ in,
                              const float* __restrict__ w,
                              float* __restrict__ outp) {
    if (g_sel[6] == 0.0f) return;
    __shared__ float s[34][34];
    const int plane = blockIdx.x;
    const int c = plane % CCH;
    const float* ip = in + (size_t)plane * PLANE;
    for (int idx = threadIdx.x; idx < 34*34; idx += 256) {
        int r = idx / 34, cc = idx - r*34;
        int yy = r - 1, xx = cc - 1;
        s[r][cc] = (yy >= 0 && yy < 32 && xx >= 0 && xx < 32) ? ip[yy*32 + xx] : 0.f;
    }
    float wv[9];
#pragma unroll
    for (int k = 0; k < 9; k++) wv[k] = w[c*9 + k];
    __syncthreads();
    for (int idx = threadIdx.x; idx < PLANE; idx += 256) {
        int yy = idx >> 5, xx = idx & 31;
        float a = 0.f;
#pragma unroll
        for (int ky = 0; ky < 3; ky++)
#pragma unroll
            for (int kx = 0; kx < 3; kx++)
                a += s[yy+ky][xx+kx] * wv[ky*3+kx];
        outp[(size_t)plane * PLANE + idx] = a;
    }
}

// ---------------------------------------------------------------------------
// 3x3 max pool (pad 1) and 3x3 avg pool (count_include_pad)
// ---------------------------------------------------------------------------
__global__ void maxpool_kernel(const float* __restrict__ in, float* __restrict__ outp) {
    if (g_sel[1] == 0.0f) return;
    __shared__ float s[34][34];
    const int plane = blockIdx.x;
    const float* ip = in + (size_t)plane * PLANE;
    for (int idx = threadIdx.x; idx < 34*34; idx += 256) {
        int r = idx / 34, cc = idx - r*34;
        int yy = r - 1, xx = cc - 1;
        s[r][cc] = (yy >= 0 && yy < 32 && xx >= 0 && xx < 32) ? ip[yy*32 + xx] : -3.0e38f;
    }
    __syncthreads();
    for (int idx = threadIdx.x; idx < PLANE; idx += 256) {
        int yy = idx >> 5, xx = idx & 31;
        float m = -3.0e38f;
#pragma unroll
        for (int ky = 0; ky < 3; ky++)
#pragma unroll
            for (int kx = 0; kx < 3; kx++)
                m = fmaxf(m, s[yy+ky][xx+kx]);
        outp[(size_t)plane * PLANE + idx] = m;
    }
}

__global__ void avgpool_kernel(const float* __restrict__ in, float* __restrict__ outp) {
    if (g_sel[2] == 0.0f) return;
    __shared__ float s[34][34];
    const int plane = blockIdx.x;
    const float* ip = in + (size_t)plane * PLANE;
    for (int idx = threadIdx.x; idx < 34*34; idx += 256) {
        int r = idx / 34, cc = idx - r*34;
        int yy = r - 1, xx = cc - 1;
        s[r][cc] = (yy >= 0 && yy < 32 && xx >= 0 && xx < 32) ? ip[yy*32 + xx] : 0.f;
    }
    __syncthreads();
    const float inv9 = 1.0f / 9.0f;
    for (int idx = threadIdx.x; idx < PLANE; idx += 256) {
        int yy = idx >> 5, xx = idx & 31;
        float a = 0.f;
#pragma unroll
        for (int ky = 0; ky < 3; ky++)
#pragma unroll
            for (int kx = 0; kx < 3; kx++)
                a += s[yy+ky][xx+kx];
        outp[(size_t)plane * PLANE + idx] = a * inv9;
    }
}

// ---------------------------------------------------------------------------
// Per-channel mean/var -> fused BN scale/shift (sel folded in)
// ---------------------------------------------------------------------------
__global__ void stats_kernel(const float* __restrict__ y,
                             const float* __restrict__ g,
                             const float* __restrict__ b,
                             int selIdx) {
    const float sel = (selIdx >= 0) ? g_sel[selIdx] : 1.0f;
    if (sel == 0.0f) return;
    const int c = blockIdx.x;
    const float* base = y + (size_t)c * PLANE;
    float s = 0.f, s2 = 0.f;
    for (int idx = threadIdx.x; idx < NHW; idx += 256) {
        int n = idx >> 10, i = idx & 1023;
        float v = base[(size_t)n * (CCH * PLANE) + i];
        s += v; s2 += v * v;
    }
    __shared__ float rs[256], rs2[256];
    rs[threadIdx.x] = s; rs2[threadIdx.x] = s2;
    __syncthreads();
    for (int o = 128; o > 0; o >>= 1) {
        if (threadIdx.x < o) { rs[threadIdx.x] += rs[threadIdx.x+o]; rs2[threadIdx.x] += rs2[threadIdx.x+o]; }
        __syncthreads();
    }
    if (threadIdx.x == 0) {
        float m   = rs[0] * (1.0f / (float)NHW);
        float var = rs2[0] * (1.0f / (float)NHW) - m * m;
        float inv = rsqrtf(var + 1e-5f);
        float A   = g[c] * inv;
        g_A[c] = sel * A;
        g_B[c] = sel * (b[c] - m * A);
    }
}

// ---------------------------------------------------------------------------
// Elementwise kernels (float4, channel derived from linear index)
// ---------------------------------------------------------------------------
__global__ void norm_relu_kernel(float* __restrict__ h) {
    size_t i4 = (size_t)blockIdx.x * 256 + threadIdx.x;
    int c = (int)((i4 >> 8) & 255);
    float A = g_A[c], Bv = g_B[c];
    float4 v = reinterpret_cast<float4*>(h)[i4];
    v.x = fmaxf(v.x * A + Bv, 0.f);
    v.y = fmaxf(v.y * A + Bv, 0.f);
    v.z = fmaxf(v.z * A + Bv, 0.f);
    v.w = fmaxf(v.w * A + Bv, 0.f);
    reinterpret_cast<float4*>(h)[i4] = v;
}

__global__ void init_out_kernel(float* __restrict__ out, const float* __restrict__ h) {
    size_t i4 = (size_t)blockIdx.x * 256 + threadIdx.x;
    float s = g_sel[3];
    float4 v = reinterpret_cast<const float4*>(h)[i4];
    v.x *= s; v.y *= s; v.z *= s; v.w *= s;
    reinterpret_cast<float4*>(out)[i4] = v;
}

__global__ void accum_kernel(float* __restrict__ out, const float* __restrict__ y, int selIdx) {
    if (g_sel[selIdx] == 0.0f) return;
    size_t i4 = (size_t)blockIdx.x * 256 + threadIdx.x;
    int c = (int)((i4 >> 8) & 255);
    float A = g_A[c], Bv = g_B[c];
    float4 v = reinterpret_cast<const float4*>(y)[i4];
    float4 o = reinterpret_cast<float4*>(out)[i4];
    o.x += v.x * A + Bv;
    o.y += v.y * A + Bv;
    o.z += v.z * A + Bv;
    o.w += v.w * A + Bv;
    reinterpret_cast<float4*>(out)[i4] = o;
}

// ---------------------------------------------------------------------------
// Launch sequence (graph-capturable, allocation-free)
// ---------------------------------------------------------------------------
extern "C" void kernel_launch(void* const* d_in, const int* in_sizes, int n_in,
                              void* d_out, int out_size) {
    const float* x    = (const float*)d_in[0];
    const float* aw   = (const float*)d_in[1];
    const float* w_in = (const float*)d_in[2];
    const float* g_in = (const float*)d_in[3];
    const float* b_in = (const float*)d_in[4];
    const float* w3   = (const float*)d_in[5];
    const float* g3   = (const float*)d_in[6];
    const float* b3   = (const float*)d_in[7];
    const float* w5   = (const float*)d_in[8];
    const float* g5   = (const float*)d_in[9];
    const float* b5   = (const float*)d_in[10];
    const float* w_dw = (const float*)d_in[11];
    const float* w_pw = (const float*)d_in[12];
    const float* gs   = (const float*)d_in[13];
    const float* bs   = (const float*)d_in[14];
    const float* wd   = (const float*)d_in[15];
    const float* gd   = (const float*)d_in[16];
    const float* bd   = (const float*)d_in[17];
    const float* gmp  = (const float*)d_in[18];
    const float* bmp  = (const float*)d_in[19];
    const float* gap  = (const float*)d_in[20];
    const float* bap  = (const float*)d_in[21];
    float* out = (float*)d_out;

    float *h, *y, *t;
    cudaGetSymbolAddress((void**)&h, g_h);
    cudaGetSymbolAddress((void**)&y, g_y);
    cudaGetSymbolAddress((void**)&t, g_t);

    const dim3 convGrid(8, BATCH, CCH / 64);
    const int  eltGrid = NTOT / 4 / 256;   // 16384

    // mixture weights
    sel_kernel<<<1, 32>>>(aw);

    // input transition: conv1x1 -> BN -> ReLU (h)
    conv_kernel<1,1,1,16><<<convGrid, 256>>>(x, w_in, h, CIN_X, CCH, -1);
    stats_kernel<<<CCH, 256>>>(h, g_in, b_in, -1);
    norm_relu_kernel<<<eltGrid, 256>>>(h);

    // out = sel[3] * h (also clears poison)
    init_out_kernel<<<eltGrid, 256>>>(out, h);

    // op 1: max_pool_3x3
    maxpool_kernel<<<NPLANES, 256>>>(h, y);
    stats_kernel<<<CCH, 256>>>(y, gmp, bmp, 1);
    accum_kernel<<<eltGrid, 256>>>(out, y, 1);

    // op 2: avg_pool_3x3
    avgpool_kernel<<<NPLANES, 256>>>(h, y);
    stats_kernel<<<CCH, 256>>>(y, gap, bap, 2);
    accum_kernel<<<eltGrid, 256>>>(out, y, 2);

    // op 4: conv_3x3
    conv_kernel<3,3,1,8><<<convGrid, 256>>>(h, w3, y, CCH, CCH, 4);
    stats_kernel<<<CCH, 256>>>(y, g3, b3, 4);
    accum_kernel<<<eltGrid, 256>>>(out, y, 4);

    // op 5: conv_5x5
    conv_kernel<5,5,1,4><<<convGrid, 256>>>(h, w5, y, CCH, CCH, 5);
    stats_kernel<<<CCH, 256>>>(y, g5, b5, 5);
    accum_kernel<<<eltGrid, 256>>>(out, y, 5);

    // op 6: sep_conv_3x3 (depthwise 3x3 -> pointwise 1x1)
    dwconv_kernel<<<NPLANES, 256>>>(h, w_dw, t);
    conv_kernel<1,1,1,16><<<convGrid, 256>>>(t, w_pw, y, CCH, CCH, 6);
    stats_kernel<<<CCH, 256>>>(y, gs, bs, 6);
    accum_kernel<<<eltGrid, 256>>>(out, y, 6);

    // op 7: dil_conv_3x3 (dilation 2, pad 2)
    conv_kernel<3,3,2,8><<<convGrid, 256>>>(h, wd, y, CCH, CCH, 7);
    stats_kernel<<<CCH, 256>>>(y, gd, bd, 7);
    accum_kernel<<<eltGrid, 256>>>(out, y, 7);
}

// round 16
// speedup vs baseline: 2.8251x; 2.8251x over previous
#include <cuda_runtime.h>
#include <cuda_bf16.h>
#include <math.h>
#include <stdint.h>

#define BATCH 64
#define CCH   256
#define PLANE 1024
#define NPLANES (BATCH*CCH)
#define NTOT (16777216u)
#define NHW  65536

__device__ __forceinline__ uint32_t f2bf(float v) {
    return (uint32_t)__bfloat16_as_ushort(__float2bfloat16(v));
}
__device__ __forceinline__ float bf2f(uint32_t b) {
    return __bfloat162float(__ushort_as_bfloat16((unsigned short)b));
}

// Warp-level bf16 MMA, fp32 accum (PTX ISA 7.0+, works on compute_103)
#define MMA16816(d, a, b0, b1) \
    asm volatile("mma.sync.aligned.m16n8k16.row.col.f32.bf16.bf16.f32 " \
        "{%0,%1,%2,%3}, {%4,%5,%6,%7}, {%8,%9}, {%0,%1,%2,%3};" \
        : "+f"((d)[0]), "+f"((d)[1]), "+f"((d)[2]), "+f"((d)[3]) \
        : "r"((a)[0]), "r"((a)[1]), "r"((a)[2]), "r"((a)[3]), "r"(b0), "r"(b1))

// ---------------- device scratch ----------------
__device__ float g_h[NTOT];
__device__ float g_y[NTOT];
__device__ float g_t[NTOT];
__device__ float g_sel[8];
__device__ float g_A[CCH];
__device__ float g_B[CCH];
// fragment-ordered split weights: up to 100 chunks x 16384 halfwords
__device__ unsigned short g_wh[1638400];
__device__ unsigned short g_wl[1638400];

// ---------------- sel ----------------
__global__ void sel_kernel(const float* __restrict__ aw) {
    if (threadIdx.x != 0) return;
    float w[8]; float mx = -1e30f;
    for (int i = 0; i < 8; i++) { w[i] = aw[i]; mx = fmaxf(mx, w[i]); }
    float s = 0.f;
    for (int i = 0; i < 8; i++) { w[i] = expf(w[i] - mx); s += w[i]; }
    for (int i = 0; i < 8; i++) w[i] /= s;
    float sel[8], tmp[8];
    for (int i = 0; i < 8; i++) { sel[i] = 0.f; tmp[i] = w[i]; }
    for (int t = 0; t < 3; t++) {
        int bi = 0; float bv = tmp[0];
        for (int i = 1; i < 8; i++) if (tmp[i] > bv) { bv = tmp[i]; bi = i; }
        sel[bi] = bv; tmp[bi] = -1e30f;
    }
    float ss = 0.f;
    for (int i = 0; i < 8; i++) { if (sel[i] < 0.01f) sel[i] = 0.f; ss += sel[i]; }
    ss = fmaxf(ss, 1e-12f);
    for (int i = 0; i < 8; i++) g_sel[i] = sel[i] / ss;
}

// ---------------- weight reorder + hi/lo split into B-fragment order ----------------
// k = tap*Cin + ci (tap-major). chunk c = k/64, s = (k%64)/16, kk = k%16.
// Within an n8 tile (t = co/8): lane = (co%8)*4 + (kk%8)/2, reg = kk/8, half = kk&1.
__global__ void reorder_kernel(const float* __restrict__ wgt, int Cin, int KK, int selIdx) {
    if (selIdx >= 0 && g_sel[selIdx] == 0.0f) return;
    int K = KK * Cin;
    long long idx = (long long)blockIdx.x * 256 + threadIdx.x;
    if (idx >= (long long)256 * K) return;
    int co = (int)(idx / K);
    int k  = (int)(idx - (long long)co * K);
    int tap = k / Cin, ci = k - tap * Cin;
    float v = wgt[((size_t)co * Cin + ci) * KK + tap];
    uint32_t h = f2bf(v);
    uint32_t l = f2bf(v - bf2f(h));
    int c = k >> 6, s = (k >> 4) & 3, kk = k & 15;
    int t = co >> 3;
    int lane = (co & 7) * 4 + ((kk & 7) >> 1);
    int reg  = kk >> 3;
    int half = kk & 1;
    size_t H = ((size_t)c * 16384) + ((size_t)t * 512) + (size_t)s * 128
             + (size_t)(lane * 2 + reg) * 2 + half;
    g_wh[H] = (unsigned short)h;
    g_wl[H] = (unsigned short)l;
}

// ---------------- tensor-core conv (mma.sync, bf16 2-split, fp32 accum) ----------------
// Grid (512, 2): bx = spatial tile (64 imgs x 8 row-tiles of 4 rows), by = cout half.
// CTA tile M=128 x N=128; 8 warps = (4 m-warps) x (2 n-warps); warp = m32 x n64.
// Smem words: A_hi[0,4096) A_lo[4096,8192) B_hi[8192,12288) B_lo[12288,16384)
#define TC_SMEM 65536
__global__ __launch_bounds__(256, 2) void tc_conv(
    const float* __restrict__ in, float* __restrict__ outp,
    int Cin, int kdim, int dil, int selIdx)
{
    if (selIdx >= 0 && g_sel[selIdx] == 0.0f) return;
    extern __shared__ uint32_t sw[];
    const int tid = threadIdx.x;
    const int l = tid & 31, w = tid >> 5;
    const int st = blockIdx.x, q = blockIdx.y;
    const int n = st >> 3;
    const int ybase = (st & 7) * 4;
    const int wm = w >> 1, wn = w & 1;
    const int pad = (kdim - 1) * dil / 2;
    const int chunks = (kdim * kdim * Cin) >> 6;

    float acc[2][8][4];
#pragma unroll
    for (int a = 0; a < 2; a++)
#pragma unroll
        for (int j = 0; j < 8; j++)
#pragma unroll
            for (int r = 0; r < 4; r++) acc[a][j][r] = 0.f;

    for (int c = 0; c < chunks; c++) {
        __syncthreads();
        // ---- build A (fragment order, hi+lo); this thread owns m-tile mt = w ----
        {
            int gk = c << 6;
            int tap = gk / Cin, cr = gk - tap * Cin;
            int dy = (tap / kdim) * dil - pad;
            int dx = (tap % kdim) * dil - pad;
#pragma unroll
            for (int s = 0; s < 4; s++) {
#pragma unroll
                for (int a = 0; a < 4; a++) {
                    int m = w * 16 + (l >> 2) + (a & 1) * 8;
                    int iy = ybase + (m >> 5) + dy;
                    int ix = (m & 31) + dx;
                    int p = (l & 3) + ((a >> 1) << 2);       // k-pair in 0..7
                    int ch = cr + 2 * (s * 8 + p);
                    float v0 = 0.f, v1 = 0.f;
                    if (iy >= 0 && iy < 32 && ix >= 0 && ix < 32) {
                        const float* sp = in + ((size_t)n * Cin + ch) * PLANE + iy * 32 + ix;
                        v0 = sp[0]; v1 = sp[PLANE];
                    }
                    uint32_t h0 = f2bf(v0), h1 = f2bf(v1);
                    uint32_t l0 = f2bf(v0 - bf2f(h0)), l1 = f2bf(v1 - bf2f(h1));
                    int widx = (w * 4 + s) * 128 + l * 4 + a;
                    sw[widx]        = h0 | (h1 << 16);
                    sw[4096 + widx] = l0 | (l1 << 16);
                }
            }
        }
        // ---- copy B (verbatim, already fragment-ordered) ----
        {
            const uint4* sh = (const uint4*)(g_wh + (size_t)c * 16384 + (size_t)q * 8192);
            const uint4* sl = (const uint4*)(g_wl + (size_t)c * 16384 + (size_t)q * 8192);
            uint4* dh = (uint4*)(sw + 8192);
            uint4* dl = (uint4*)(sw + 12288);
#pragma unroll
            for (int i = 0; i < 4; i++) {
                dh[i * 256 + tid] = sh[i * 256 + tid];
                dl[i * 256 + tid] = sl[i * 256 + tid];
            }
        }
        __syncthreads();
        // ---- MMA: 4 k16 steps x 8 n-tiles x 2 m-tiles x 3 chains ----
#pragma unroll
        for (int s = 0; s < 4; s++) {
            uint32_t Ah[2][4], Al[2][4];
#pragma unroll
            for (int mt = 0; mt < 2; mt++) {
                int mtg = wm * 2 + mt;
                const uint4* pa = (const uint4*)&sw[(mtg * 4 + s) * 128 + (l << 2)];
                uint4 va = pa[0];
                Ah[mt][0] = va.x; Ah[mt][1] = va.y; Ah[mt][2] = va.z; Ah[mt][3] = va.w;
                uint4 vb = pa[1024];     // +4096 words
                Al[mt][0] = vb.x; Al[mt][1] = vb.y; Al[mt][2] = vb.z; Al[mt][3] = vb.w;
            }
#pragma unroll
            for (int j = 0; j < 8; j++) {
                int boff = 8192 + ((wn * 8 + j) * 4 + s) * 64 + l * 2;
                uint32_t bh0 = sw[boff], bh1 = sw[boff + 1];
                uint32_t bl0 = sw[boff + 4096], bl1 = sw[boff + 4097];
#pragma unroll
                for (int mt = 0; mt < 2; mt++) {
                    MMA16816(acc[mt][j], Ah[mt], bh0, bh1);
                    MMA16816(acc[mt][j], Ah[mt], bl0, bl1);
                    MMA16816(acc[mt][j], Al[mt], bh0, bh1);
                }
            }
        }
    }

    // ---- store D (fp32, NCHW) ----
#pragma unroll
    for (int mt = 0; mt < 2; mt++) {
#pragma unroll
        for (int j = 0; j < 8; j++) {
            int m0 = wm * 32 + mt * 16 + (l >> 2);
            int co = q * 128 + wn * 64 + j * 8 + (l & 3) * 2;
            int y0 = ybase + (m0 >> 5), x0 = m0 & 31;
            int m1 = m0 + 8;
            int y1 = ybase + (m1 >> 5), x1 = m1 & 31;
            size_t b0 = ((size_t)n * CCH + co) * PLANE;
            size_t b1 = b0 + PLANE;                      // co+1
            outp[b0 + y0 * 32 + x0] = acc[mt][j][0];
            outp[b1 + y0 * 32 + x0] = acc[mt][j][1];
            outp[b0 + y1 * 32 + x1] = acc[mt][j][2];
            outp[b1 + y1 * 32 + x1] = acc[mt][j][3];
        }
    }
}

// ---------------- depthwise / pools ----------------
__global__ void dwconv_kernel(const float* __restrict__ in, const float* __restrict__ w,
                              float* __restrict__ outp) {
    if (g_sel[6] == 0.0f) return;
    __shared__ float s[34][34];
    const int plane = blockIdx.x;
    const int c = plane % CCH;
    const float* ip = in + (size_t)plane * PLANE;
    for (int idx = threadIdx.x; idx < 34*34; idx += 256) {
        int r = idx / 34, cc = idx - r*34;
        int yy = r - 1, xx = cc - 1;
        s[r][cc] = (yy >= 0 && yy < 32 && xx >= 0 && xx < 32) ? ip[yy*32 + xx] : 0.f;
    }
    float wv[9];
#pragma unroll
    for (int k = 0; k < 9; k++) wv[k] = w[c*9 + k];
    __syncthreads();
    for (int idx = threadIdx.x; idx < PLANE; idx += 256) {
        int yy = idx >> 5, xx = idx & 31;
        float a = 0.f;
#pragma unroll
        for (int ky = 0; ky < 3; ky++)
#pragma unroll
            for (int kx = 0; kx < 3; kx++)
                a += s[yy+ky][xx+kx] * wv[ky*3+kx];
        outp[(size_t)plane * PLANE + idx] = a;
    }
}

__global__ void maxpool_kernel(const float* __restrict__ in, float* __restrict__ outp) {
    if (g_sel[1] == 0.0f) return;
    __shared__ float s[34][34];
    const int plane = blockIdx.x;
    const float* ip = in + (size_t)plane * PLANE;
    for (int idx = threadIdx.x; idx < 34*34; idx += 256) {
        int r = idx / 34, cc = idx - r*34;
        int yy = r - 1, xx = cc - 1;
        s[r][cc] = (yy >= 0 && yy < 32 && xx >= 0 && xx < 32) ? ip[yy*32 + xx] : -3.0e38f;
    }
    __syncthreads();
    for (int idx = threadIdx.x; idx < PLANE; idx += 256) {
        int yy = idx >> 5, xx = idx & 31;
        float m = -3.0e38f;
#pragma unroll
        for (int ky = 0; ky < 3; ky++)
#pragma unroll
            for (int kx = 0; kx < 3; kx++)
                m = fmaxf(m, s[yy+ky][xx+kx]);
        outp[(size_t)plane * PLANE + idx] = m;
    }
}

__global__ void avgpool_kernel(const float* __restrict__ in, float* __restrict__ outp) {
    if (g_sel[2] == 0.0f) return;
    __shared__ float s[34][34];
    const int plane = blockIdx.x;
    const float* ip = in + (size_t)plane * PLANE;
    for (int idx = threadIdx.x; idx < 34*34; idx += 256) {
        int r = idx / 34, cc = idx - r*34;
        int yy = r - 1, xx = cc - 1;
        s[r][cc] = (yy >= 0 && yy < 32 && xx >= 0 && xx < 32) ? ip[yy*32 + xx] : 0.f;
    }
    __syncthreads();
    const float inv9 = 1.0f / 9.0f;
    for (int idx = threadIdx.x; idx < PLANE; idx += 256) {
        int yy = idx >> 5, xx = idx & 31;
        float a = 0.f;
#pragma unroll
        for (int ky = 0; ky < 3; ky++)
#pragma unroll
            for (int kx = 0; kx < 3; kx++)
                a += s[yy+ky][xx+kx];
        outp[(size_t)plane * PLANE + idx] = a * inv9;
    }
}

// ---------------- BN stats + elementwise ----------------
__global__ void stats_kernel(const float* __restrict__ y, const float* __restrict__ g,
                             const float* __restrict__ b, int selIdx) {
    const float sel = (selIdx >= 0) ? g_sel[selIdx] : 1.0f;
    if (sel == 0.0f) return;
    const int c = blockIdx.x;
    const float* base = y + (size_t)c * PLANE;
    float s = 0.f, s2 = 0.f;
    for (int idx = threadIdx.x; idx < NHW; idx += 256) {
        int n = idx >> 10, i = idx & 1023;
        float v = base[(size_t)n * (CCH * PLANE) + i];
        s += v; s2 += v * v;
    }
    __shared__ float rs[256], rs2[256];
    rs[threadIdx.x] = s; rs2[threadIdx.x] = s2;
    __syncthreads();
    for (int o = 128; o > 0; o >>= 1) {
        if (threadIdx.x < o) { rs[threadIdx.x] += rs[threadIdx.x+o]; rs2[threadIdx.x] += rs2[threadIdx.x+o]; }
        __syncthreads();
    }
    if (threadIdx.x == 0) {
        float m   = rs[0] * (1.0f / (float)NHW);
        float var = rs2[0] * (1.0f / (float)NHW) - m * m;
        float inv = rsqrtf(var + 1e-5f);
        float A   = g[c] * inv;
        g_A[c] = sel * A;
        g_B[c] = sel * (b[c] - m * A);
    }
}

__global__ void norm_relu_kernel(float* __restrict__ h) {
    size_t i4 = (size_t)blockIdx.x * 256 + threadIdx.x;
    int c = (int)((i4 >> 8) & 255);
    float A = g_A[c], Bv = g_B[c];
    float4 v = reinterpret_cast<float4*>(h)[i4];
    v.x = fmaxf(v.x * A + Bv, 0.f);
    v.y = fmaxf(v.y * A + Bv, 0.f);
    v.z = fmaxf(v.z * A + Bv, 0.f);
    v.w = fmaxf(v.w * A + Bv, 0.f);
    reinterpret_cast<float4*>(h)[i4] = v;
}

__global__ void init_out_kernel(float* __restrict__ out, const float* __restrict__ h) {
    size_t i4 = (size_t)blockIdx.x * 256 + threadIdx.x;
    float s = g_sel[3];
    float4 v = reinterpret_cast<const float4*>(h)[i4];
    v.x *= s; v.y *= s; v.z *= s; v.w *= s;
    reinterpret_cast<float4*>(out)[i4] = v;
}

__global__ void accum_kernel(float* __restrict__ out, const float* __restrict__ y, int selIdx) {
    if (g_sel[selIdx] == 0.0f) return;
    size_t i4 = (size_t)blockIdx.x * 256 + threadIdx.x;
    int c = (int)((i4 >> 8) & 255);
    float A = g_A[c], Bv = g_B[c];
    float4 v = reinterpret_cast<const float4*>(y)[i4];
    float4 o = reinterpret_cast<float4*>(out)[i4];
    o.x += v.x * A + Bv;
    o.y += v.y * A + Bv;
    o.z += v.z * A + Bv;
    o.w += v.w * A + Bv;
    reinterpret_cast<float4*>(out)[i4] = o;
}

// ---------------- launch sequence ----------------
extern "C" void kernel_launch(void* const* d_in, const int* in_sizes, int n_in,
                              void* d_out, int out_size) {
    const float* x    = (const float*)d_in[0];
    const float* aw   = (const float*)d_in[1];
    const float* w_in = (const float*)d_in[2];
    const float* g_in = (const float*)d_in[3];
    const float* b_in = (const float*)d_in[4];
    const float* w3   = (const float*)d_in[5];
    const float* g3   = (const float*)d_in[6];
    const float* b3   = (const float*)d_in[7];
    const float* w5   = (const float*)d_in[8];
    const float* g5   = (const float*)d_in[9];
    const float* b5   = (const float*)d_in[10];
    const float* w_dw = (const float*)d_in[11];
    const float* w_pw = (const float*)d_in[12];
    const float* gs   = (const float*)d_in[13];
    const float* bs   = (const float*)d_in[14];
    const float* wd   = (const float*)d_in[15];
    const float* gd   = (const float*)d_in[16];
    const float* bd   = (const float*)d_in[17];
    const float* gmp  = (const float*)d_in[18];
    const float* bmp  = (const float*)d_in[19];
    const float* gap  = (const float*)d_in[20];
    const float* bap  = (const float*)d_in[21];
    float* out = (float*)d_out;

    float *h, *y, *t;
    cudaGetSymbolAddress((void**)&h, g_h);
    cudaGetSymbolAddress((void**)&y, g_y);
    cudaGetSymbolAddress((void**)&t, g_t);

    cudaFuncSetAttribute(tc_conv, cudaFuncAttributeMaxDynamicSharedMemorySize, TC_SMEM);

    const int eltGrid = NTOT / 4 / 256;   // 16384
    const dim3 tcGrid(512, 2);
    auto rblocks = [](int K) { return (256 * K + 255) / 256; };

    sel_kernel<<<1, 32>>>(aw);

    // input transition conv1x1 (always on)
    reorder_kernel<<<rblocks(128), 256>>>(w_in, 128, 1, -1);
    tc_conv<<<tcGrid, 256, TC_SMEM>>>(x, h, 128, 1, 1, -1);
    stats_kernel<<<CCH, 256>>>(h, g_in, b_in, -1);
    norm_relu_kernel<<<eltGrid, 256>>>(h);

    init_out_kernel<<<eltGrid, 256>>>(out, h);

    // op1: maxpool
    maxpool_kernel<<<NPLANES, 256>>>(h, y);
    stats_kernel<<<CCH, 256>>>(y, gmp, bmp, 1);
    accum_kernel<<<eltGrid, 256>>>(out, y, 1);

    // op2: avgpool
    avgpool_kernel<<<NPLANES, 256>>>(h, y);
    stats_kernel<<<CCH, 256>>>(y, gap, bap, 2);
    accum_kernel<<<eltGrid, 256>>>(out, y, 2);

    // op4: conv3x3
    reorder_kernel<<<rblocks(2304), 256>>>(w3, 256, 9, 4);
    tc_conv<<<tcGrid, 256, TC_SMEM>>>(h, y, 256, 3, 1, 4);
    stats_kernel<<<CCH, 256>>>(y, g3, b3, 4);
    accum_kernel<<<eltGrid, 256>>>(out, y, 4);

    // op5: conv5x5
    reorder_kernel<<<rblocks(6400), 256>>>(w5, 256, 25, 5);
    tc_conv<<<tcGrid, 256, TC_SMEM>>>(h, y, 256, 5, 1, 5);
    stats_kernel<<<CCH, 256>>>(y, g5, b5, 5);
    accum_kernel<<<eltGrid, 256>>>(out, y, 5);

    // op6: sep (dw3x3 -> pw1x1)
    dwconv_kernel<<<NPLANES, 256>>>(h, w_dw, t);
    reorder_kernel<<<rblocks(256), 256>>>(w_pw, 256, 1, 6);
    tc_conv<<<tcGrid, 256, TC_SMEM>>>(t, y, 256, 1, 1, 6);
    stats_kernel<<<CCH, 256>>>(y, gs, bs, 6);
    accum_kernel<<<eltGrid, 256>>>(out, y, 6);

    // op7: dil conv3x3 (dil=2)
    reorder_kernel<<<rblocks(2304), 256>>>(wd, 256, 9, 7);
    tc_conv<<<tcGrid, 256, TC_SMEM>>>(h, y, 256, 3, 2, 7);
    stats_kernel<<<CCH, 256>>>(y, gd, bd, 7);
    accum_kernel<<<eltGrid, 256>>>(out, y, 7);
}

// round 17
// speedup vs baseline: 2.8308x; 1.0020x over previous
#include <cuda_runtime.h>
#include <cuda_bf16.h>
#include <math.h>
#include <stdint.h>

#define BATCH 64
#define CCH   256
#define PLANE 1024
#define NPLANES (BATCH*CCH)
#define NTOT (16777216u)
#define NHW  65536

__device__ __forceinline__ uint32_t f2bf(float v) {
    return (uint32_t)__bfloat16_as_ushort(__float2bfloat16(v));
}
__device__ __forceinline__ float bf2f(uint32_t b) {
    return __bfloat162float(__ushort_as_bfloat16((unsigned short)b));
}

// Warp-level bf16 MMA, fp32 accum (PTX ISA 7.0+, works on compute_103)
#define MMA16816(d, a, b0, b1) \
    asm volatile("mma.sync.aligned.m16n8k16.row.col.f32.bf16.bf16.f32 " \
        "{%0,%1,%2,%3}, {%4,%5,%6,%7}, {%8,%9}, {%0,%1,%2,%3};" \
        : "+f"((d)[0]), "+f"((d)[1]), "+f"((d)[2]), "+f"((d)[3]) \
        : "r"((a)[0]), "r"((a)[1]), "r"((a)[2]), "r"((a)[3]), "r"(b0), "r"(b1))

// ---------------- device scratch ----------------
__device__ float g_h[NTOT];
__device__ float g_y[NTOT];
__device__ float g_t[NTOT];
__device__ float g_sel[8];
__device__ float g_A[CCH];
__device__ float g_B[CCH];
// fragment-ordered split weights: up to 100 chunks x 16384 halfwords
__device__ unsigned short g_wh[1638400];
__device__ unsigned short g_wl[1638400];

// ---------------- sel ----------------
__global__ void sel_kernel(const float* __restrict__ aw) {
    if (threadIdx.x != 0) return;
    float w[8]; float mx = -1e30f;
    for (int i = 0; i < 8; i++) { w[i] = aw[i]; mx = fmaxf(mx, w[i]); }
    float s = 0.f;
    for (int i = 0; i < 8; i++) { w[i] = expf(w[i] - mx); s += w[i]; }
    for (int i = 0; i < 8; i++) w[i] /= s;
    float sel[8], tmp[8];
    for (int i = 0; i < 8; i++) { sel[i] = 0.f; tmp[i] = w[i]; }
    for (int t = 0; t < 3; t++) {
        int bi = 0; float bv = tmp[0];
        for (int i = 1; i < 8; i++) if (tmp[i] > bv) { bv = tmp[i]; bi = i; }
        sel[bi] = bv; tmp[bi] = -1e30f;
    }
    float ss = 0.f;
    for (int i = 0; i < 8; i++) { if (sel[i] < 0.01f) sel[i] = 0.f; ss += sel[i]; }
    ss = fmaxf(ss, 1e-12f);
    for (int i = 0; i < 8; i++) g_sel[i] = sel[i] / ss;
}

// ---------------- weight reorder + hi/lo split into B-fragment order ----------------
// k = tap*Cin + ci (tap-major). chunk c = k/64, s = (k%64)/16, kk = k%16.
// Within an n8 tile (t = co/8): lane = (co%8)*4 + (kk%8)/2, reg = kk/8, half = kk&1.
__global__ void reorder_kernel(const float* __restrict__ wgt, int Cin, int KK, int selIdx) {
    if (selIdx >= 0 && g_sel[selIdx] == 0.0f) return;
    int K = KK * Cin;
    long long idx = (long long)blockIdx.x * 256 + threadIdx.x;
    if (idx >= (long long)256 * K) return;
    int co = (int)(idx / K);
    int k  = (int)(idx - (long long)co * K);
    int tap = k / Cin, ci = k - tap * Cin;
    float v = wgt[((size_t)co * Cin + ci) * KK + tap];
    uint32_t h = f2bf(v);
    uint32_t l = f2bf(v - bf2f(h));
    int c = k >> 6, s = (k >> 4) & 3, kk = k & 15;
    int t = co >> 3;
    int lane = (co & 7) * 4 + ((kk & 7) >> 1);
    int reg  = kk >> 3;
    int half = kk & 1;
    size_t H = ((size_t)c * 16384) + ((size_t)t * 512) + (size_t)s * 128
             + (size_t)(lane * 2 + reg) * 2 + half;
    g_wh[H] = (unsigned short)h;
    g_wl[H] = (unsigned short)l;
}

// ---------------- tensor-core conv (mma.sync, bf16 2-split, fp32 accum) ----------------
// Grid (512, 2): bx = spatial tile (64 imgs x 8 row-tiles of 4 rows), by = cout half.
// CTA tile M=128 x N=128; 8 warps = (4 m-warps) x (2 n-warps); warp = m32 x n64.
// Smem words: A_hi[0,4096) A_lo[4096,8192) B_hi[8192,12288) B_lo[12288,16384)
#define TC_SMEM 65536
__global__ __launch_bounds__(256, 2) void tc_conv(
    const float* __restrict__ in, float* __restrict__ outp,
    int Cin, int kdim, int dil, int selIdx)
{
    if (selIdx >= 0 && g_sel[selIdx] == 0.0f) return;
    extern __shared__ uint32_t sw[];
    const int tid = threadIdx.x;
    const int l = tid & 31, w = tid >> 5;
    const int st = blockIdx.x, q = blockIdx.y;
    const int n = st >> 3;
    const int ybase = (st & 7) * 4;
    const int wm = w >> 1, wn = w & 1;
    const int pad = (kdim - 1) * dil / 2;
    const int chunks = (kdim * kdim * Cin) >> 6;

    float acc[2][8][4];
#pragma unroll
    for (int a = 0; a < 2; a++)
#pragma unroll
        for (int j = 0; j < 8; j++)
#pragma unroll
            for (int r = 0; r < 4; r++) acc[a][j][r] = 0.f;

    for (int c = 0; c < chunks; c++) {
        __syncthreads();
        // ---- build A (fragment order, hi+lo); this thread owns m-tile mt = w ----
        {
            int gk = c << 6;
            int tap = gk / Cin, cr = gk - tap * Cin;
            int dy = (tap / kdim) * dil - pad;
            int dx = (tap % kdim) * dil - pad;
#pragma unroll
            for (int s = 0; s < 4; s++) {
#pragma unroll
                for (int a = 0; a < 4; a++) {
                    int m = w * 16 + (l >> 2) + (a & 1) * 8;
                    int iy = ybase + (m >> 5) + dy;
                    int ix = (m & 31) + dx;
                    int p = (l & 3) + ((a >> 1) << 2);       // k-pair in 0..7
                    int ch = cr + 2 * (s * 8 + p);
                    float v0 = 0.f, v1 = 0.f;
                    if (iy >= 0 && iy < 32 && ix >= 0 && ix < 32) {
                        const float* sp = in + ((size_t)n * Cin + ch) * PLANE + iy * 32 + ix;
                        v0 = sp[0]; v1 = sp[PLANE];
                    }
                    uint32_t h0 = f2bf(v0), h1 = f2bf(v1);
                    uint32_t l0 = f2bf(v0 - bf2f(h0)), l1 = f2bf(v1 - bf2f(h1));
                    int widx = (w * 4 + s) * 128 + l * 4 + a;
                    sw[widx]        = h0 | (h1 << 16);
                    sw[4096 + widx] = l0 | (l1 << 16);
                }
            }
        }
        // ---- copy B (verbatim, already fragment-ordered) ----
        {
            const uint4* sh = (const uint4*)(g_wh + (size_t)c * 16384 + (size_t)q * 8192);
            const uint4* sl = (const uint4*)(g_wl + (size_t)c * 16384 + (size_t)q * 8192);
            uint4* dh = (uint4*)(sw + 8192);
            uint4* dl = (uint4*)(sw + 12288);
#pragma unroll
            for (int i = 0; i < 4; i++) {
                dh[i * 256 + tid] = sh[i * 256 + tid];
                dl[i * 256 + tid] = sl[i * 256 + tid];
            }
        }
        __syncthreads();
        // ---- MMA: 4 k16 steps x 8 n-tiles x 2 m-tiles x 3 chains ----
#pragma unroll
        for (int s = 0; s < 4; s++) {
            uint32_t Ah[2][4], Al[2][4];
#pragma unroll
            for (int mt = 0; mt < 2; mt++) {
                int mtg = wm * 2 + mt;
                const uint4* pa = (const uint4*)&sw[(mtg * 4 + s) * 128 + (l << 2)];
                uint4 va = pa[0];
                Ah[mt][0] = va.x; Ah[mt][1] = va.y; Ah[mt][2] = va.z; Ah[mt][3] = va.w;
                uint4 vb = pa[1024];     // +4096 words
                Al[mt][0] = vb.x; Al[mt][1] = vb.y; Al[mt][2] = vb.z; Al[mt][3] = vb.w;
            }
#pragma unroll
            for (int j = 0; j < 8; j++) {
                int boff = 8192 + ((wn * 8 + j) * 4 + s) * 64 + l * 2;
                uint32_t bh0 = sw[boff], bh1 = sw[boff + 1];
                uint32_t bl0 = sw[boff + 4096], bl1 = sw[boff + 4097];
#pragma unroll
                for (int mt = 0; mt < 2; mt++) {
                    MMA16816(acc[mt][j], Ah[mt], bh0, bh1);
                    MMA16816(acc[mt][j], Ah[mt], bl0, bl1);
                    MMA16816(acc[mt][j], Al[mt], bh0, bh1);
                }
            }
        }
    }

    // ---- store D (fp32, NCHW) ----
#pragma unroll
    for (int mt = 0; mt < 2; mt++) {
#pragma unroll
        for (int j = 0; j < 8; j++) {
            int m0 = wm * 32 + mt * 16 + (l >> 2);
            int co = q * 128 + wn * 64 + j * 8 + (l & 3) * 2;
            int y0 = ybase + (m0 >> 5), x0 = m0 & 31;
            int m1 = m0 + 8;
            int y1 = ybase + (m1 >> 5), x1 = m1 & 31;
            size_t b0 = ((size_t)n * CCH + co) * PLANE;
            size_t b1 = b0 + PLANE;                      // co+1
            outp[b0 + y0 * 32 + x0] = acc[mt][j][0];
            outp[b1 + y0 * 32 + x0] = acc[mt][j][1];
            outp[b0 + y1 * 32 + x1] = acc[mt][j][2];
            outp[b1 + y1 * 32 + x1] = acc[mt][j][3];
        }
    }
}

// ---------------- depthwise / pools ----------------
__global__ void dwconv_kernel(const float* __restrict__ in, const float* __restrict__ w,
                              float* __restrict__ outp) {
    if (g_sel[6] == 0.0f) return;
    __shared__ float s[34][34];
    const int plane = blockIdx.x;
    const int c = plane % CCH;
    const float* ip = in + (size_t)plane * PLANE;
    for (int idx = threadIdx.x; idx < 34*34; idx += 256) {
        int r = idx / 34, cc = idx - r*34;
        int yy = r - 1, xx = cc - 1;
        s[r][cc] = (yy >= 0 && yy < 32 && xx >= 0 && xx < 32) ? ip[yy*32 + xx] : 0.f;
    }
    float wv[9];
#pragma unroll
    for (int k = 0; k < 9; k++) wv[k] = w[c*9 + k];
    __syncthreads();
    for (int idx = threadIdx.x; idx < PLANE; idx += 256) {
        int yy = idx >> 5, xx = idx & 31;
        float a = 0.f;
#pragma unroll
        for (int ky = 0; ky < 3; ky++)
#pragma unroll
            for (int kx = 0; kx < 3; kx++)
                a += s[yy+ky][xx+kx] * wv[ky*3+kx];
        outp[(size_t)plane * PLANE + idx] = a;
    }
}

__global__ void maxpool_kernel(const float* __restrict__ in, float* __restrict__ outp) {
    if (g_sel[1] == 0.0f) return;
    __shared__ float s[34][34];
    const int plane = blockIdx.x;
    const float* ip = in + (size_t)plane * PLANE;
    for (int idx = threadIdx.x; idx < 34*34; idx += 256) {
        int r = idx / 34, cc = idx - r*34;
        int yy = r - 1, xx = cc - 1;
        s[r][cc] = (yy >= 0 && yy < 32 && xx >= 0 && xx < 32) ? ip[yy*32 + xx] : -3.0e38f;
    }
    __syncthreads();
    for (int idx = threadIdx.x; idx < PLANE; idx += 256) {
        int yy = idx >> 5, xx = idx & 31;
        float m = -3.0e38f;
#pragma unroll
        for (int ky = 0; ky < 3; ky++)
#pragma unroll
            for (int kx = 0; kx < 3; kx++)
                m = fmaxf(m, s[yy+ky][xx+kx]);
        outp[(size_t)plane * PLANE + idx] = m;
    }
}

__global__ void avgpool_kernel(const float* __restrict__ in, float* __restrict__ outp) {
    if (g_sel[2] == 0.0f) return;
    __shared__ float s[34][34];
    const int plane = blockIdx.x;
    const float* ip = in + (size_t)plane * PLANE;
    for (int idx = threadIdx.x; idx < 34*34; idx += 256) {
        int r = idx / 34, cc = idx - r*34;
        int yy = r - 1, xx = cc - 1;
        s[r][cc] = (yy >= 0 && yy < 32 && xx >= 0 && xx < 32) ? ip[yy*32 + xx] : 0.f;
    }
    __syncthreads();
    const float inv9 = 1.0f / 9.0f;
    for (int idx = threadIdx.x; idx < PLANE; idx += 256) {
        int yy = idx >> 5, xx = idx & 31;
        float a = 0.f;
#pragma unroll
        for (int ky = 0; ky < 3; ky++)
#pragma unroll
            for (int kx = 0; kx < 3; kx++)
                a += s[yy+ky][xx+kx];
        outp[(size_t)plane * PLANE + idx] = a * inv9;
    }
}

// ---------------- BN stats + elementwise ----------------
__global__ void stats_kernel(const float* __restrict__ y, const float* __restrict__ g,
                             const float* __restrict__ b, int selIdx) {
    const float sel = (selIdx >= 0) ? g_sel[selIdx] : 1.0f;
    if (sel == 0.0f) return;
    const int c = blockIdx.x;
    const float* base = y + (size_t)c * PLANE;
    float s = 0.f, s2 = 0.f;
    for (int idx = threadIdx.x; idx < NHW; idx += 256) {
        int n = idx >> 10, i = idx & 1023;
        float v = base[(size_t)n * (CCH * PLANE) + i];
        s += v; s2 += v * v;
    }
    __shared__ float rs[256], rs2[256];
    rs[threadIdx.x] = s; rs2[threadIdx.x] = s2;
    __syncthreads();
    for (int o = 128; o > 0; o >>= 1) {
        if (threadIdx.x < o) { rs[threadIdx.x] += rs[threadIdx.x+o]; rs2[threadIdx.x] += rs2[threadIdx.x+o]; }
        __syncthreads();
    }
    if (threadIdx.x == 0) {
        float m   = rs[0] * (1.0f / (float)NHW);
        float var = rs2[0] * (1.0f / (float)NHW) - m * m;
        float inv = rsqrtf(var + 1e-5f);
        float A   = g[c] * inv;
        g_A[c] = sel * A;
        g_B[c] = sel * (b[c] - m * A);
    }
}

__global__ void norm_relu_kernel(float* __restrict__ h) {
    size_t i4 = (size_t)blockIdx.x * 256 + threadIdx.x;
    int c = (int)((i4 >> 8) & 255);
    float A = g_A[c], Bv = g_B[c];
    float4 v = reinterpret_cast<float4*>(h)[i4];
    v.x = fmaxf(v.x * A + Bv, 0.f);
    v.y = fmaxf(v.y * A + Bv, 0.f);
    v.z = fmaxf(v.z * A + Bv, 0.f);
    v.w = fmaxf(v.w * A + Bv, 0.f);
    reinterpret_cast<float4*>(h)[i4] = v;
}

__global__ void init_out_kernel(float* __restrict__ out, const float* __restrict__ h) {
    size_t i4 = (size_t)blockIdx.x * 256 + threadIdx.x;
    float s = g_sel[3];
    float4 v = reinterpret_cast<const float4*>(h)[i4];
    v.x *= s; v.y *= s; v.z *= s; v.w *= s;
    reinterpret_cast<float4*>(out)[i4] = v;
}

__global__ void accum_kernel(float* __restrict__ out, const float* __restrict__ y, int selIdx) {
    if (g_sel[selIdx] == 0.0f) return;
    size_t i4 = (size_t)blockIdx.x * 256 + threadIdx.x;
    int c = (int)((i4 >> 8) & 255);
    float A = g_A[c], Bv = g_B[c];
    float4 v = reinterpret_cast<const float4*>(y)[i4];
    float4 o = reinterpret_cast<float4*>(out)[i4];
    o.x += v.x * A + Bv;
    o.y += v.y * A + Bv;
    o.z += v.z * A + Bv;
    o.w += v.w * A + Bv;
    reinterpret_cast<float4*>(out)[i4] = o;
}

// ---------------- launch sequence ----------------
extern "C" void kernel_launch(void* const* d_in, const int* in_sizes, int n_in,
                              void* d_out, int out_size) {
    const float* x    = (const float*)d_in[0];
    const float* aw   = (const float*)d_in[1];
    const float* w_in = (const float*)d_in[2];
    const float* g_in = (const float*)d_in[3];
    const float* b_in = (const float*)d_in[4];
    const float* w3   = (const float*)d_in[5];
    const float* g3   = (const float*)d_in[6];
    const float* b3   = (const float*)d_in[7];
    const float* w5   = (const float*)d_in[8];
    const float* g5   = (const float*)d_in[9];
    const float* b5   = (const float*)d_in[10];
    const float* w_dw = (const float*)d_in[11];
    const float* w_pw = (const float*)d_in[12];
    const float* gs   = (const float*)d_in[13];
    const float* bs   = (const float*)d_in[14];
    const float* wd   = (const float*)d_in[15];
    const float* gd   = (const float*)d_in[16];
    const float* bd   = (const float*)d_in[17];
    const float* gmp  = (const float*)d_in[18];
    const float* bmp  = (const float*)d_in[19];
    const float* gap  = (const float*)d_in[20];
    const float* bap  = (const float*)d_in[21];
    float* out = (float*)d_out;

    float *h, *y, *t;
    cudaGetSymbolAddress((void**)&h, g_h);
    cudaGetSymbolAddress((void**)&y, g_y);
    cudaGetSymbolAddress((void**)&t, g_t);

    cudaFuncSetAttribute(tc_conv, cudaFuncAttributeMaxDynamicSharedMemorySize, TC_SMEM);

    const int eltGrid = NTOT / 4 / 256;   // 16384
    const dim3 tcGrid(512, 2);
    auto rblocks = [](int K) { return (256 * K + 255) / 256; };

    sel_kernel<<<1, 32>>>(aw);

    // input transition conv1x1 (always on)
    reorder_kernel<<<rblocks(128), 256>>>(w_in, 128, 1, -1);
    tc_conv<<<tcGrid, 256, TC_SMEM>>>(x, h, 128, 1, 1, -1);
    stats_kernel<<<CCH, 256>>>(h, g_in, b_in, -1);
    norm_relu_kernel<<<eltGrid, 256>>>(h);

    init_out_kernel<<<eltGrid, 256>>>(out, h);

    // op1: maxpool
    maxpool_kernel<<<NPLANES, 256>>>(h, y);
    stats_kernel<<<CCH, 256>>>(y, gmp, bmp, 1);
    accum_kernel<<<eltGrid, 256>>>(out, y, 1);

    // op2: avgpool
    avgpool_kernel<<<NPLANES, 256>>>(h, y);
    stats_kernel<<<CCH, 256>>>(y, gap, bap, 2);
    accum_kernel<<<eltGrid, 256>>>(out, y, 2);

    // op4: conv3x3
    reorder_kernel<<<rblocks(2304), 256>>>(w3, 256, 9, 4);
    tc_conv<<<tcGrid, 256, TC_SMEM>>>(h, y, 256, 3, 1, 4);
    stats_kernel<<<CCH, 256>>>(y, g3, b3, 4);
    accum_kernel<<<eltGrid, 256>>>(out, y, 4);

    // op5: conv5x5
    reorder_kernel<<<rblocks(6400), 256>>>(w5, 256, 25, 5);
    tc_conv<<<tcGrid, 256, TC_SMEM>>>(h, y, 256, 5, 1, 5);
    stats_kernel<<<CCH, 256>>>(y, g5, b5, 5);
    accum_kernel<<<eltGrid, 256>>>(out, y, 5);

    // op6: sep (dw3x3 -> pw1x1)
    dwconv_kernel<<<NPLANES, 256>>>(h, w_dw, t);
    reorder_kernel<<<rblocks(256), 256>>>(w_pw, 256, 1, 6);
    tc_conv<<<tcGrid, 256, TC_SMEM>>>(t, y, 256, 1, 1, 6);
    stats_kernel<<<CCH, 256>>>(y, gs, bs, 6);
    accum_kernel<<<eltGrid, 256>>>(out, y, 6);

    // op7: dil conv3x3 (dil=2)
    reorder_kernel<<<rblocks(2304), 256>>>(wd, 256, 9, 7);
    tc_conv<<<tcGrid, 256, TC_SMEM>>>(h, y, 256, 3, 2, 7);
    stats_kernel<<<CCH, 256>>>(y, gd, bd, 7);
    accum_kernel<<<eltGrid, 256>>>(out, y, 7);
}